// round 14
// baseline (speedup 1.0000x reference)
#include <cuda_runtime.h>
#include <math.h>

#define B_ 4
#define N_ 2048
#define NB_ 10
#define P_ 5
#define CPD 16   // 15 dims + ||row||^2 in slot 15
#define CH 128   // streamed points per smem tile (== 32*NT)
#define NT 4     // fixed rows per thread
#define NRED 64  // partial-reduce blocks (16 per batch)
#define PBLK 32  // prep blocks per batch (N_/64 elems per block)

// ---------------- scratch (no allocations allowed) ----------------
// g_best_u / g_k1 / g_k2 use INVERTED keys with atomicMax so that the
// zero-initialized state (module load, and re-zeroed by final_kernel each
// launch) is the reduction identity. min(k) == ~max(~k); ties -> smallest idx.
__device__ float g_pred_cp[B_*N_*CPD];
__device__ float g_gt_c   [B_*N_*CPD];   // compacted succ gt rows (+pad)
__device__ int   g_cidx   [B_*N_];       // compact slot -> original index
__device__ int   g_nch    [B_];          // padded chunk count per batch
__device__ int   g_cnt  [B_] = {0,0,0,0};  // per-batch compaction counters
__device__ int   g_bdone[B_] = {0,0,0,0};  // per-batch prep-block completion tickets
__device__ unsigned           g_best_u[B_*N_];  // ~min-key (0 = infinity)
__device__ unsigned long long g_k1[B_*N_];      // ~packed (val,idx), normal
__device__ unsigned long long g_k2[B_*N_];      // ~packed (val,idx), sym
__device__ float g_ew  [B_*N_];   // succ*(cos_d + cos_a + off)
__device__ float g_sbce[B_*N_];   // score bce per point
__device__ float g_part[NRED][5]; // per-block partials: s, ew, g2p, adds, bce
__device__ unsigned g_done;       // completion counter for last-block combine

typedef unsigned long long ull;

__device__ __forceinline__ ull pack2(float lo, float hi) {
    ull r; asm("mov.b64 %0,{%1,%2};" : "=l"(r) : "f"(lo), "f"(hi)); return r;
}
__device__ __forceinline__ void unpack2(ull v, float& lo, float& hi) {
    asm("mov.b64 {%0,%1},%2;" : "=f"(lo), "=f"(hi) : "l"(v));
}
__device__ __forceinline__ ull fma2(ull a, ull b, ull c) {
    ull d; asm("fma.rn.f32x2 %0,%1,%2,%3;" : "=l"(d) : "l"(a), "l"(b), "l"(c)); return d;
}
__device__ __forceinline__ ull mul2(ull a, ull b) {
    ull d; asm("mul.rn.f32x2 %0,%1,%2;" : "=l"(d) : "l"(a), "l"(b)); return d;
}
// fast softplus: max(x,0) + log(1 + exp(-|x|)); argument of __logf is in (1,2]
__device__ __forceinline__ float softplus_fast(float x) {
    return fmaxf(x, 0.0f) + __logf(1.0f + __expf(-fabsf(x)));
}
#define F_INF __int_as_float(0x7f800000)

// ---------------- kernel 1: prep, 2 warp-roles per 64 elements ----------------
__global__ __launch_bounds__(128) void prep_kernel(
    const float* __restrict__ gd, const float* __restrict__ ad,
    const float* __restrict__ goh, const float* __restrict__ pp,
    const float* __restrict__ bsh, const float* __restrict__ dl,
    const float* __restrict__ ol, const float* __restrict__ succ,
    const float* __restrict__ al, const float* __restrict__ bv,
    const float* __restrict__ bw, const float* __restrict__ cp)
{
    __shared__ float s_off[64];
    int tid  = threadIdx.x;
    int role = tid >> 6;          // 0 = A, 1 = B
    int li   = tid & 63;
    int i    = blockIdx.x * 64 + li;
    int b    = i >> 11;
    int n    = i & (N_ - 1);

    float cosd_cosa = 0.0f;  // role B carry
    float s_b = 0.0f;

    if (role == 0) {
        // ---------------- role A ----------------
        if (i == 0) g_done = 0;

        float bx = gd[i*3+0], by = gd[i*3+1], bz = gd[i*3+2];
        float ax = ad[i*3+0], ay = ad[i*3+1], az = ad[i*3+2];
        float px = pp[i*3+0], py = pp[i*3+1], pz = pp[i*3+2];

        int kp = 0; float xm = goh[i*NB_];
        #pragma unroll
        for (int k = 1; k < NB_; k++) { float v = goh[i*NB_+k]; if (v > xm) { xm = v; kp = k; } }
        float thp = bv[kp];

        float cx = ay*bz - az*by, cy = az*bx - ax*bz, cz = ax*by - ay*bx;
        float tx = px + 0.5f*thp*bx, ty = py + 0.5f*thp*by, tz = pz + 0.5f*thp*bz;
        {
            float row[16]; float nrm = 0.0f;
            #pragma unroll
            for (int p = 0; p < P_; p++) {
                float c0 = cp[p*3+0], c1 = cp[p*3+1], c2 = cp[p*3+2];
                float vx = bx*c0 + cx*c1 + ax*c2 + tx;
                float vy = by*c0 + cy*c1 + ay*c2 + ty;
                float vz = bz*c0 + cz*c1 + az*c2 + tz;
                row[p*3+0] = vx; row[p*3+1] = vy; row[p*3+2] = vz;
                nrm += vx*vx + vy*vy + vz*vz;
            }
            row[15] = nrm;
            float4* po = (float4*)(g_pred_cp + (size_t)i * CPD);
            #pragma unroll
            for (int q = 0; q < 4; q++) po[q] = make_float4(row[q*4], row[q*4+1], row[q*4+2], row[q*4+3]);
        }

        // bce: y*sp(-x) + (1-y)*sp(x) == sp(x) - y*x  exactly (y,s in {0,1})
        float off0 = 0.0f, off1 = 0.0f;
        #pragma unroll
        for (int k = 0; k < NB_; k += 2) {
            float x0 = goh[i*NB_+k],   y0 = ol[i*NB_+k];
            float x1 = goh[i*NB_+k+1], y1 = ol[i*NB_+k+1];
            off0 += bw[k]   * (softplus_fast(x0) - y0*x0);
            off1 += bw[k+1] * (softplus_fast(x1) - y1*x1);
        }
        s_off[li] = (off0 + off1) * (1.0f / NB_);

        float s = succ[i];
        float h = bsh[i];
        g_sbce[i] = softplus_fast(h) - s*h;
    } else {
        // ---------------- role B ----------------
        float bx = gd[i*3+0], by = gd[i*3+1], bz = gd[i*3+2];
        float ax = ad[i*3+0], ay = ad[i*3+1], az = ad[i*3+2];
        float px = pp[i*3+0], py = pp[i*3+1], pz = pp[i*3+2];

        int kg = 0; float ym = ol[i*NB_];
        #pragma unroll
        for (int k = 1; k < NB_; k++) { float v = ol[i*NB_+k]; if (v > ym) { ym = v; kg = k; } }
        float thg = bv[kg];

        float s = succ[i];
        s_b = s;
        float gbx = dl[i*3+0], gby = dl[i*3+1], gbz = dl[i*3+2];
        float gax = al[i*3+0], gay = al[i*3+1], gaz = al[i*3+2];
        float gcx = gay*gbz - gaz*gby, gcy = gaz*gbx - gax*gbz, gcz = gax*gby - gay*gbx;
        float gtx = px + 0.5f*thg*gbx, gty = py + 0.5f*thg*gby, gtz = pz + 0.5f*thg*gbz;
        {
            float row[16]; float nrm = 0.0f;
            #pragma unroll
            for (int p = 0; p < P_; p++) {
                float c0 = cp[p*3+0], c1 = cp[p*3+1], c2 = cp[p*3+2];
                float vx = gbx*c0 + gcx*c1 + gax*c2 + gtx;
                float vy = gby*c0 + gcy*c1 + gay*c2 + gty;
                float vz = gbz*c0 + gcz*c1 + gaz*c2 + gtz;
                row[p*3+0] = vx; row[p*3+1] = vy; row[p*3+2] = vz;
                nrm += vx*vx + vy*vy + vz*vz;
            }
            row[15] = nrm;
            if (s > 0.5f) {
                int slot = atomicAdd(&g_cnt[b], 1);
                float4* go = (float4*)(g_gt_c + ((size_t)b*N_ + slot) * CPD);
                #pragma unroll
                for (int q = 0; q < 4; q++) go[q] = make_float4(row[q*4], row[q*4+1], row[q*4+2], row[q*4+3]);
                g_cidx[(size_t)b*N_ + slot] = n;
            }
        }

        float cos_d = 1.0f - (gbx*bx + gby*by + gbz*bz);
        float proj = bx*gax + by*gay + bz*gaz;
        float ox = gax - proj*bx, oy = gay - proj*by, oz = gaz - proj*bz;
        float on = sqrtf(ox*ox + oy*oy + oz*oz);
        float inv = 1.0f / fmaxf(on, 1e-12f);
        float cos_a = 1.0f - (ox*ax + oy*ay + oz*az) * inv;
        cosd_cosa = cos_d + cos_a;
    }

    __syncthreads();
    if (role == 1) {
        g_ew[i] = s_b * (cosd_cosa + s_off[li]);
    }

    // ---- fused tail-pad: last prep block of this batch pads the compacted array ----
    __shared__ bool amLast;
    __syncthreads();
    if (tid == 0) {
        __threadfence();
        amLast = (atomicAdd(&g_bdone[b], 1) == PBLK - 1);
    }
    __syncthreads();
    if (amLast) {
        __threadfence();
        int cnt = atomicAdd(&g_cnt[b], 0);     // final value: all batch blocks done
        int pad = (cnt + CH - 1) / CH * CH;
        for (int p = cnt + tid; p < pad; p += 128) {
            float4* d = (float4*)(g_gt_c + ((size_t)b*N_ + p) * CPD);
            d[0] = make_float4(0,0,0,0);
            d[1] = make_float4(0,0,0,0);
            d[2] = make_float4(0,0,0,0);
            d[3] = make_float4(0,0,0,F_INF);   // norm = INF -> never wins a min
            g_cidx[(size_t)b*N_ + p] = 0;
        }
        if (tid == 0) {
            g_nch[b] = pad / CH;
            g_cnt[b] = 0;                      // reset for next graph replay
            g_bdone[b] = 0;
        }
    }
}

// ---------------- kernel 2: pairwise, both directions, balanced splits ----------------
// grid (16, B_, 6): z<2 dir A (stream-half), z>=2 dir B (stream-quarter).
// Reductions via atomicMax on INVERTED keys (zero-initialized identity).
__global__ __launch_bounds__(256, 2) void pair_kernel(const float* __restrict__ bsp)
{
#if __CUDA_ARCH__ >= 900
    cudaGridDependencySynchronize();
#endif
    __shared__ float4 sg[CH*5];            // stride-5 padding: conflict-free
    int b    = blockIdx.y;
    int z    = blockIdx.z;
    int tid  = threadIdx.x;
    int ns   = tid >> 3;
    int ml   = tid & 7;

    if (z < 2) {
        // ---------------- direction A ----------------
        int half = z;
        ull FP[NT][7];
        float f14[NT], fn[NT], fD0[NT], fD1[NT], fD2[NT];
        int nrow[NT];
        #pragma unroll
        for (int r = 0; r < NT; r++) {
            int n = blockIdx.x * (32*NT) + r*32 + ns;
            nrow[r] = n;
            const float4* row = (const float4*)(g_pred_cp + ((size_t)b*N_ + n) * CPD);
            float4 a0 = row[0], a1 = row[1], a2 = row[2], a3 = row[3];
            FP[r][0] = pack2(a0.x, a0.y); FP[r][1] = pack2(a0.z, a0.w);
            FP[r][2] = pack2(a1.x, a1.y); FP[r][3] = pack2(a1.z, a1.w);
            FP[r][4] = pack2(a2.x, a2.y); FP[r][5] = pack2(a2.z, a2.w);
            FP[r][6] = pack2(a3.x, a3.y);
            f14[r] = a3.z; fn[r] = a3.w;
            fD0[r] = a1.z - a2.y; fD1[r] = a1.w - a2.z; fD2[r] = a2.x - a2.w;
        }
        float minv[NT];
        #pragma unroll
        for (int r = 0; r < NT; r++) minv[r] = F_INF;

        int nch = g_nch[b];
        for (int c = half; c < nch; c += 2) {
            int mc = c * CH;
            __syncthreads();
            const float4* src = (const float4*)(g_gt_c + ((size_t)b*N_ + mc) * CPD);
            #pragma unroll
            for (int j = tid; j < CH*4; j += 256) sg[(j >> 2) * 5 + (j & 3)] = src[j];
            __syncthreads();

            #pragma unroll 2
            for (int j = 0; j < CH/8; j++) {
                int m = ml + j*8;
                const float4* sp = &sg[m*5];
                float4 s0 = sp[0], s1 = sp[1], s2 = sp[2], s3 = sp[3];
                ull S0 = pack2(s0.x, s0.y), S1 = pack2(s0.z, s0.w);
                ull S2 = pack2(s1.x, s1.y), S3 = pack2(s1.z, s1.w);
                ull S4 = pack2(s2.x, s2.y), S5 = pack2(s2.z, s2.w);
                ull S6 = pack2(s3.x, s3.y);
                float s14 = s3.z, sn = s3.w;
                float D0 = s1.z - s2.y, D1 = s1.w - s2.z, D2 = s2.x - s2.w;

                #pragma unroll
                for (int r = 0; r < NT; r++) {
                    ull a = mul2(FP[r][0], S0);
                    ull cc = mul2(FP[r][1], S1);
                    a = fma2(FP[r][2], S2, a);
                    cc = fma2(FP[r][3], S3, cc);
                    a = fma2(FP[r][4], S4, a);
                    cc = fma2(FP[r][5], S5, cc);
                    a = fma2(FP[r][6], S6, a);
                    float alo, ahi, clo, chi;
                    unpack2(a, alo, ahi); unpack2(cc, clo, chi);
                    float dot = fmaf(f14[r], s14, (alo + ahi) + (clo + chi));
                    float d1 = fmaf(-2.0f, dot, fn[r] + sn);
                    float corr = fD0[r] * D0;
                    corr = fmaf(fD1[r], D1, corr);
                    corr = fmaf(fD2[r], D2, corr);
                    float d2 = fmaf(2.0f, corr, d1);
                    minv[r] = fminf(minv[r], fminf(d1, d2));   // clamp deferred
                }
            }
        }
        #pragma unroll
        for (int r = 0; r < NT; r++) {
            float v = minv[r];
            v = fminf(v, __shfl_down_sync(0xffffffffu, v, 4));
            v = fminf(v, __shfl_down_sync(0xffffffffu, v, 2));
            v = fminf(v, __shfl_down_sync(0xffffffffu, v, 1));
            if (ml == 0)
                atomicMax(&g_best_u[(size_t)b*N_ + nrow[r]], ~__float_as_uint(fmaxf(v, 0.0f)));
        }
    } else {
        // ---------------- direction B ----------------
        int quart = z - 2;
        int padcnt = g_nch[b] * CH;
        int row0 = blockIdx.x * (32*NT);
        if (row0 >= padcnt) return;

        ull FP[NT][7];
        float f14[NT], fn[NT], fD0[NT], fD1[NT], fD2[NT];
        int orig[NT];
        #pragma unroll
        for (int r = 0; r < NT; r++) {
            int n = row0 + r*32 + ns;
            orig[r] = g_cidx[(size_t)b*N_ + n];
            const float4* row = (const float4*)(g_gt_c + ((size_t)b*N_ + n) * CPD);
            float4 a0 = row[0], a1 = row[1], a2 = row[2], a3 = row[3];
            FP[r][0] = pack2(a0.x, a0.y); FP[r][1] = pack2(a0.z, a0.w);
            FP[r][2] = pack2(a1.x, a1.y); FP[r][3] = pack2(a1.z, a1.w);
            FP[r][4] = pack2(a2.x, a2.y); FP[r][5] = pack2(a2.z, a2.w);
            FP[r][6] = pack2(a3.x, a3.y);
            f14[r] = a3.z; fn[r] = a3.w;
            fD0[r] = a1.z - a2.y; fD1[r] = a1.w - a2.z; fD2[r] = a2.x - a2.w;
        }
        ull b1[NT], b2[NT];
        #pragma unroll
        for (int r = 0; r < NT; r++) { b1[r] = ~0ull; b2[r] = ~0ull; }

        for (int c = quart; c < N_/CH; c += 4) {
            int mc = c * CH;
            __syncthreads();
            const float4* src = (const float4*)(g_pred_cp + ((size_t)b*N_ + mc) * CPD);
            #pragma unroll
            for (int j = tid; j < CH*4; j += 256) sg[(j >> 2) * 5 + (j & 3)] = src[j];
            __syncthreads();

            #pragma unroll 2
            for (int j = 0; j < CH/8; j++) {
                int m = ml + j*8;
                const float4* sp = &sg[m*5];
                float4 s0 = sp[0], s1 = sp[1], s2 = sp[2], s3 = sp[3];
                ull S0 = pack2(s0.x, s0.y), S1 = pack2(s0.z, s0.w);
                ull S2 = pack2(s1.x, s1.y), S3 = pack2(s1.z, s1.w);
                ull S4 = pack2(s2.x, s2.y), S5 = pack2(s2.z, s2.w);
                ull S6 = pack2(s3.x, s3.y);
                float s14 = s3.z, sn = s3.w;
                float D0 = s1.z - s2.y, D1 = s1.w - s2.z, D2 = s2.x - s2.w;
                unsigned idx = (unsigned)(mc + m);

                #pragma unroll
                for (int r = 0; r < NT; r++) {
                    ull a = mul2(FP[r][0], S0);
                    ull cc = mul2(FP[r][1], S1);
                    a = fma2(FP[r][2], S2, a);
                    cc = fma2(FP[r][3], S3, cc);
                    a = fma2(FP[r][4], S4, a);
                    cc = fma2(FP[r][5], S5, cc);
                    a = fma2(FP[r][6], S6, a);
                    float alo, ahi, clo, chi;
                    unpack2(a, alo, ahi); unpack2(cc, clo, chi);
                    float dot = fmaf(f14[r], s14, (alo + ahi) + (clo + chi));
                    float d1 = fmaf(-2.0f, dot, fn[r] + sn);
                    float corr = fD0[r] * D0;
                    corr = fmaf(fD1[r], D1, corr);
                    corr = fmaf(fD2[r], D2, corr);
                    float d2 = fmaf(2.0f, corr, d1);
                    d1 = fmaxf(d1, 0.0f);
                    d2 = fmaxf(d2, 0.0f);
                    ull k1 = ((ull)__float_as_uint(d1) << 32) | idx;
                    ull k2 = ((ull)__float_as_uint(d2) << 32) | idx;
                    if (k1 < b1[r]) b1[r] = k1;
                    if (k2 < b2[r]) b2[r] = k2;
                }
            }
        }
        #pragma unroll
        for (int r = 0; r < NT; r++) {
            ull v1 = b1[r], v2 = b2[r], o;
            o = __shfl_down_sync(0xffffffffu, v1, 4); if (o < v1) v1 = o;
            o = __shfl_down_sync(0xffffffffu, v1, 2); if (o < v1) v1 = o;
            o = __shfl_down_sync(0xffffffffu, v1, 1); if (o < v1) v1 = o;
            o = __shfl_down_sync(0xffffffffu, v2, 4); if (o < v2) v2 = o;
            o = __shfl_down_sync(0xffffffffu, v2, 2); if (o < v2) v2 = o;
            o = __shfl_down_sync(0xffffffffu, v2, 1); if (o < v2) v2 = o;
            if (ml == 0) {
                atomicMax(&g_k1[(size_t)b*N_ + orig[r]], ~v1);
                atomicMax(&g_k2[(size_t)b*N_ + orig[r]], ~v2);
            }
        }
    }
}

// ---------------- kernel 3: final reduction (64 blocks x 128, last-block combine)
// Also re-zeros g_best_u / g_k1 / g_k2 for the next graph replay.
__global__ __launch_bounds__(128) void final_kernel(const float* __restrict__ succ,
                                                    const float* __restrict__ bsp,
                                                    float* __restrict__ out)
{
#if __CUDA_ARCH__ >= 900
    cudaGridDependencySynchronize();
#endif
    int i = blockIdx.x * 128 + threadIdx.x;   // block -> contiguous 128, same batch
    int b = i >> 11;
    float sv = succ[i];
    float ev = g_ew[i];
    ull nk1 = g_k1[i], nk2 = g_k2[i];         // inverted keys
    unsigned bu = g_best_u[i];                // inverted min-key (0 = infinity)
    float cv = g_sbce[i];

    // reset for next replay (each thread owns its own slot)
    g_k1[i] = 0ull; g_k2[i] = 0ull; g_best_u[i] = 0u;

    float gv = 0.0f;
    if (sv > 0.5f) {
        ull k1 = ~nk1, k2 = ~nk2;
        float m1 = __uint_as_float((unsigned)(k1 >> 32));
        float m2 = __uint_as_float((unsigned)(k2 >> 32));
        int i1 = (int)(k1 & 0xFFFFFFFFu);
        int i2 = (int)(k2 & 0xFFFFFFFFu);
        int idx = (m2 < m1) ? i2 : i1;
        gv = sv * bsp[(size_t)b*N_ + idx] * fminf(m1, m2);
    }

    unsigned bv_ = ~bu;
    float ma = (bu == 0u || bv_ >= 0x7f800000u) ? 0.0f : sqrtf(__uint_as_float(bv_));
    float av = bsp[i] * ma;

    #define WR(v) { v += __shfl_xor_sync(0xffffffffu, v, 16); \
                    v += __shfl_xor_sync(0xffffffffu, v, 8);  \
                    v += __shfl_xor_sync(0xffffffffu, v, 4);  \
                    v += __shfl_xor_sync(0xffffffffu, v, 2);  \
                    v += __shfl_xor_sync(0xffffffffu, v, 1); }
    WR(sv) WR(ev) WR(gv) WR(av) WR(cv)
    #undef WR

    __shared__ float red[4][5];
    __shared__ bool amLast;
    int w = threadIdx.x >> 5, l = threadIdx.x & 31;
    if (l == 0) { red[w][0]=sv; red[w][1]=ev; red[w][2]=gv; red[w][3]=av; red[w][4]=cv; }
    __syncthreads();

    if (threadIdx.x == 0) {
        float a0=0,a1=0,a2=0,a3=0,a4=0;
        #pragma unroll
        for (int w2 = 0; w2 < 4; w2++) {
            a0+=red[w2][0]; a1+=red[w2][1]; a2+=red[w2][2]; a3+=red[w2][3]; a4+=red[w2][4];
        }
        g_part[blockIdx.x][0]=a0; g_part[blockIdx.x][1]=a1; g_part[blockIdx.x][2]=a2;
        g_part[blockIdx.x][3]=a3; g_part[blockIdx.x][4]=a4;
        __threadfence();
        amLast = (atomicAdd(&g_done, 1u) == NRED - 1);
    }
    __syncthreads();

    if (amLast && threadIdx.x < 32) {
        int t = threadIdx.x;
        __threadfence();
        // lane t carries partial rows 2t and 2t+1 (same batch: 16 rows/batch)
        float s  = __ldcg(&g_part[2*t][0]) + __ldcg(&g_part[2*t+1][0]);
        float e  = __ldcg(&g_part[2*t][1]) + __ldcg(&g_part[2*t+1][1]);
        float g  = __ldcg(&g_part[2*t][2]) + __ldcg(&g_part[2*t+1][2]);
        float ad = __ldcg(&g_part[2*t][3]) + __ldcg(&g_part[2*t+1][3]);
        float bc = __ldcg(&g_part[2*t][4]) + __ldcg(&g_part[2*t+1][4]);

        // per-batch sums: groups of 8 consecutive lanes (8 lanes x 2 rows = 1 batch)
        s += __shfl_xor_sync(0xffffffffu, s, 1); s += __shfl_xor_sync(0xffffffffu, s, 2); s += __shfl_xor_sync(0xffffffffu, s, 4);
        e += __shfl_xor_sync(0xffffffffu, e, 1); e += __shfl_xor_sync(0xffffffffu, e, 2); e += __shfl_xor_sync(0xffffffffu, e, 4);
        g += __shfl_xor_sync(0xffffffffu, g, 1); g += __shfl_xor_sync(0xffffffffu, g, 2); g += __shfl_xor_sync(0xffffffffu, g, 4);
        // global sums
        ad += __shfl_xor_sync(0xffffffffu, ad, 1); ad += __shfl_xor_sync(0xffffffffu, ad, 2);
        ad += __shfl_xor_sync(0xffffffffu, ad, 4); ad += __shfl_xor_sync(0xffffffffu, ad, 8);
        ad += __shfl_xor_sync(0xffffffffu, ad, 16);
        bc += __shfl_xor_sync(0xffffffffu, bc, 1); bc += __shfl_xor_sync(0xffffffffu, bc, 2);
        bc += __shfl_xor_sync(0xffffffffu, bc, 4); bc += __shfl_xor_sync(0xffffffffu, bc, 8);
        bc += __shfl_xor_sync(0xffffffffu, bc, 16);

        float S0 = __shfl_sync(0xffffffffu, s, 0),  E0 = __shfl_sync(0xffffffffu, e, 0),  G0 = __shfl_sync(0xffffffffu, g, 0);
        float S1 = __shfl_sync(0xffffffffu, s, 8),  E1 = __shfl_sync(0xffffffffu, e, 8),  G1 = __shfl_sync(0xffffffffu, g, 8);
        float S2 = __shfl_sync(0xffffffffu, s, 16), E2 = __shfl_sync(0xffffffffu, e, 16), G2 = __shfl_sync(0xffffffffu, g, 16);
        float S3 = __shfl_sync(0xffffffffu, s, 24), E3 = __shfl_sync(0xffffffffu, e, 24), G3 = __shfl_sync(0xffffffffu, g, 24);

        if (t == 0) {
            float tot = (E0 + G0) / fmaxf(S0, 1.0f)
                      + (E1 + G1) / fmaxf(S1, 1.0f)
                      + (E2 + G2) / fmaxf(S2, 1.0f)
                      + (E3 + G3) / fmaxf(S3, 1.0f);
            tot *= (1.0f / B_);
            tot += 10.0f * ad * (1.0f / (B_ * N_));
            tot += bc * (1.0f / (B_ * N_));
            out[0] = tot;
        }
    }
}

// ---------------- launch (PDL chain: prep -> pair -> final) ----------------
extern "C" void kernel_launch(void* const* d_in, const int* in_sizes, int n_in,
                              void* d_out, int out_size)
{
    const float* gd   = (const float*)d_in[0];
    const float* ad   = (const float*)d_in[1];
    const float* goh  = (const float*)d_in[2];
    const float* pp   = (const float*)d_in[3];
    const float* bsp  = (const float*)d_in[4];
    const float* bsh  = (const float*)d_in[5];
    const float* dl   = (const float*)d_in[6];
    const float* ol   = (const float*)d_in[7];
    const float* succ = (const float*)d_in[8];
    const float* al   = (const float*)d_in[9];
    const float* bv   = (const float*)d_in[10];
    const float* bw   = (const float*)d_in[11];
    const float* cp   = (const float*)d_in[12];
    float* out = (float*)d_out;

    prep_kernel<<<128, 128>>>(gd, ad, goh, pp, bsh, dl, ol, succ, al, bv, bw, cp);

    cudaLaunchAttribute attr[1];
    attr[0].id = cudaLaunchAttributeProgrammaticStreamSerialization;
    attr[0].val.programmaticStreamSerializationAllowed = 1;

    cudaLaunchConfig_t cfg2 = {};
    cfg2.gridDim  = dim3(N_ / (32*NT), B_, 6);
    cfg2.blockDim = dim3(256, 1, 1);
    cfg2.attrs = attr;
    cfg2.numAttrs = 1;
    cudaLaunchKernelEx(&cfg2, pair_kernel, bsp);

    cudaLaunchConfig_t cfg3 = {};
    cfg3.gridDim  = dim3(NRED, 1, 1);
    cfg3.blockDim = dim3(128, 1, 1);
    cfg3.attrs = attr;
    cfg3.numAttrs = 1;
    cudaLaunchKernelEx(&cfg3, final_kernel, succ, bsp, out);
}

// round 15
// speedup vs baseline: 1.0626x; 1.0626x over previous
#include <cuda_runtime.h>
#include <math.h>

#define B_ 4
#define N_ 2048
#define NB_ 10
#define P_ 5
#define CPD 16   // 15 dims + ||row||^2 in slot 15
#define CH 128   // streamed points per smem tile (== 32*NT)
#define NT 4     // fixed rows per thread
#define NRED 32  // partial-reduce blocks (8 per batch)
#define PBLK 32  // prep blocks per batch (N_/64 elems per block)

// ---------------- scratch (no allocations allowed) ----------------
__device__ float g_pred_cp[B_*N_*CPD];
__device__ float g_gt_c   [B_*N_*CPD];   // compacted succ gt rows (+pad)
__device__ int   g_cidx   [B_*N_];       // compact slot -> original index
__device__ int   g_nch    [B_];          // padded chunk count per batch
__device__ int   g_cnt  [B_] = {0,0,0,0};  // per-batch compaction counters
__device__ int   g_bdone[B_] = {0,0,0,0};  // per-batch prep-block completion tickets
__device__ unsigned           g_best_u[B_*N_];  // pred->gt min (uint-ordered float)
__device__ unsigned long long g_k1[B_*N_];      // gt->pred packed (val,idx), normal
__device__ unsigned long long g_k2[B_*N_];      // gt->pred packed (val,idx), sym
__device__ float g_ew  [B_*N_];   // succ*(cos_d + cos_a + off)
__device__ float g_sbce[B_*N_];   // score bce per point
__device__ float g_part[NRED][5]; // per-block partials: s, ew, g2p, adds, bce
__device__ unsigned g_done;       // completion counter for last-block combine

typedef unsigned long long ull;

__device__ __forceinline__ void unpack2(ull v, float& lo, float& hi) {
    asm("mov.b64 {%0,%1},%2;" : "=f"(lo), "=f"(hi) : "l"(v));
}
__device__ __forceinline__ ull fma2(ull a, ull b, ull c) {
    ull d; asm("fma.rn.f32x2 %0,%1,%2,%3;" : "=l"(d) : "l"(a), "l"(b), "l"(c)); return d;
}
__device__ __forceinline__ ull mul2(ull a, ull b) {
    ull d; asm("mul.rn.f32x2 %0,%1,%2;" : "=l"(d) : "l"(a), "l"(b)); return d;
}
// fast softplus: max(x,0) + log(1 + exp(-|x|)); argument of __logf is in (1,2]
__device__ __forceinline__ float softplus_fast(float x) {
    return fmaxf(x, 0.0f) + __logf(1.0f + __expf(-fabsf(x)));
}
#define F_INF __int_as_float(0x7f800000)

// ---------------- kernel 1: prep, 2 warp-roles per 64 elements ----------------
__global__ __launch_bounds__(128) void prep_kernel(
    const float* __restrict__ gd, const float* __restrict__ ad,
    const float* __restrict__ goh, const float* __restrict__ pp,
    const float* __restrict__ bsh, const float* __restrict__ dl,
    const float* __restrict__ ol, const float* __restrict__ succ,
    const float* __restrict__ al, const float* __restrict__ bv,
    const float* __restrict__ bw, const float* __restrict__ cp)
{
    __shared__ float s_off[64];
    int tid  = threadIdx.x;
    int role = tid >> 6;          // 0 = A, 1 = B
    int li   = tid & 63;
    int i    = blockIdx.x * 64 + li;
    int b    = i >> 11;
    int n    = i & (N_ - 1);

    float cosd_cosa = 0.0f;  // role B carry
    float s_b = 0.0f;

    if (role == 0) {
        // ---------------- role A ----------------
        if (i == 0) g_done = 0;
        g_best_u[i] = 0x7f800000u;
        g_k1[i] = 0xFFFFFFFFFFFFFFFFull;
        g_k2[i] = 0xFFFFFFFFFFFFFFFFull;

        float bx = gd[i*3+0], by = gd[i*3+1], bz = gd[i*3+2];
        float ax = ad[i*3+0], ay = ad[i*3+1], az = ad[i*3+2];
        float px = pp[i*3+0], py = pp[i*3+1], pz = pp[i*3+2];

        int kp = 0; float xm = goh[i*NB_];
        #pragma unroll
        for (int k = 1; k < NB_; k++) { float v = goh[i*NB_+k]; if (v > xm) { xm = v; kp = k; } }
        float thp = bv[kp];

        float cx = ay*bz - az*by, cy = az*bx - ax*bz, cz = ax*by - ay*bx;
        float tx = px + 0.5f*thp*bx, ty = py + 0.5f*thp*by, tz = pz + 0.5f*thp*bz;
        {
            float row[16]; float nrm = 0.0f;
            #pragma unroll
            for (int p = 0; p < P_; p++) {
                float c0 = cp[p*3+0], c1 = cp[p*3+1], c2 = cp[p*3+2];
                float vx = bx*c0 + cx*c1 + ax*c2 + tx;
                float vy = by*c0 + cy*c1 + ay*c2 + ty;
                float vz = bz*c0 + cz*c1 + az*c2 + tz;
                row[p*3+0] = vx; row[p*3+1] = vy; row[p*3+2] = vz;
                nrm += vx*vx + vy*vy + vz*vz;
            }
            row[15] = nrm;
            float4* po = (float4*)(g_pred_cp + (size_t)i * CPD);
            #pragma unroll
            for (int q = 0; q < 4; q++) po[q] = make_float4(row[q*4], row[q*4+1], row[q*4+2], row[q*4+3]);
        }

        // bce: y*sp(-x) + (1-y)*sp(x) == sp(x) - y*x  exactly (y,s in {0,1})
        float off0 = 0.0f, off1 = 0.0f;
        #pragma unroll
        for (int k = 0; k < NB_; k += 2) {
            float x0 = goh[i*NB_+k],   y0 = ol[i*NB_+k];
            float x1 = goh[i*NB_+k+1], y1 = ol[i*NB_+k+1];
            off0 += bw[k]   * (softplus_fast(x0) - y0*x0);
            off1 += bw[k+1] * (softplus_fast(x1) - y1*x1);
        }
        s_off[li] = (off0 + off1) * (1.0f / NB_);

        float s = succ[i];
        float h = bsh[i];
        g_sbce[i] = softplus_fast(h) - s*h;
    } else {
        // ---------------- role B ----------------
        float bx = gd[i*3+0], by = gd[i*3+1], bz = gd[i*3+2];
        float ax = ad[i*3+0], ay = ad[i*3+1], az = ad[i*3+2];
        float px = pp[i*3+0], py = pp[i*3+1], pz = pp[i*3+2];

        int kg = 0; float ym = ol[i*NB_];
        #pragma unroll
        for (int k = 1; k < NB_; k++) { float v = ol[i*NB_+k]; if (v > ym) { ym = v; kg = k; } }
        float thg = bv[kg];

        float s = succ[i];
        s_b = s;
        float gbx = dl[i*3+0], gby = dl[i*3+1], gbz = dl[i*3+2];
        float gax = al[i*3+0], gay = al[i*3+1], gaz = al[i*3+2];
        float gcx = gay*gbz - gaz*gby, gcy = gaz*gbx - gax*gbz, gcz = gax*gby - gay*gbx;
        float gtx = px + 0.5f*thg*gbx, gty = py + 0.5f*thg*gby, gtz = pz + 0.5f*thg*gbz;
        {
            float row[16]; float nrm = 0.0f;
            #pragma unroll
            for (int p = 0; p < P_; p++) {
                float c0 = cp[p*3+0], c1 = cp[p*3+1], c2 = cp[p*3+2];
                float vx = gbx*c0 + gcx*c1 + gax*c2 + gtx;
                float vy = gby*c0 + gcy*c1 + gay*c2 + gty;
                float vz = gbz*c0 + gcz*c1 + gaz*c2 + gtz;
                row[p*3+0] = vx; row[p*3+1] = vy; row[p*3+2] = vz;
                nrm += vx*vx + vy*vy + vz*vz;
            }
            row[15] = nrm;
            if (s > 0.5f) {
                int slot = atomicAdd(&g_cnt[b], 1);
                float4* go = (float4*)(g_gt_c + ((size_t)b*N_ + slot) * CPD);
                #pragma unroll
                for (int q = 0; q < 4; q++) go[q] = make_float4(row[q*4], row[q*4+1], row[q*4+2], row[q*4+3]);
                g_cidx[(size_t)b*N_ + slot] = n;
            }
        }

        float cos_d = 1.0f - (gbx*bx + gby*by + gbz*bz);
        float proj = bx*gax + by*gay + bz*gaz;
        float ox = gax - proj*bx, oy = gay - proj*by, oz = gaz - proj*bz;
        float on = sqrtf(ox*ox + oy*oy + oz*oz);
        float inv = 1.0f / fmaxf(on, 1e-12f);
        float cos_a = 1.0f - (ox*ax + oy*ay + oz*az) * inv;
        cosd_cosa = cos_d + cos_a;
    }

    __syncthreads();
    if (role == 1) {
        g_ew[i] = s_b * (cosd_cosa + s_off[li]);
    }

    // ---- fused tail-pad: last prep block of this batch pads the compacted array ----
    __shared__ bool amLast;
    __syncthreads();
    if (tid == 0) {
        __threadfence();
        amLast = (atomicAdd(&g_bdone[b], 1) == PBLK - 1);
    }
    __syncthreads();
    if (amLast) {
        __threadfence();
        int cnt = atomicAdd(&g_cnt[b], 0);     // final value: all batch blocks done
        int pad = (cnt + CH - 1) / CH * CH;
        for (int p = cnt + tid; p < pad; p += 128) {
            float4* d = (float4*)(g_gt_c + ((size_t)b*N_ + p) * CPD);
            d[0] = make_float4(0,0,0,0);
            d[1] = make_float4(0,0,0,0);
            d[2] = make_float4(0,0,0,0);
            d[3] = make_float4(0,0,0,F_INF);   // norm = INF -> never wins a min
            g_cidx[(size_t)b*N_ + p] = 0;
        }
        if (tid == 0) {
            g_nch[b] = pad / CH;
            g_cnt[b] = 0;                      // reset for next graph replay
            g_bdone[b] = 0;
        }
    }
}

// ---------------- kernel 2: pairwise, both directions, balanced splits ----------------
// grid (16, B_, 6): z<2 dir A (stream-half), z>=2 dir B (stream-quarter).
// Streamed smem layout: stride-5 float4 per point; slots 0-3 = the 16 floats
// (read back as ulonglong2 pairs -> packed f32x2 operands for free), slot 4 =
// precomputed (D0,D1,D2,_) for the sym-swap correction.
__global__ __launch_bounds__(256, 2) void pair_kernel(const float* __restrict__ bsp)
{
#if __CUDA_ARCH__ >= 900
    cudaGridDependencySynchronize();
#endif
    __shared__ float4 sg[CH*5];            // stride-5 padding: conflict-free
    int b    = blockIdx.y;
    int z    = blockIdx.z;
    int tid  = threadIdx.x;
    int ns   = tid >> 3;
    int ml   = tid & 7;

    if (z < 2) {
        // ---------------- direction A ----------------
        int half = z;
        ull FP[NT][7];
        float f14[NT], fn[NT], fD0[NT], fD1[NT], fD2[NT];
        int nrow[NT];
        #pragma unroll
        for (int r = 0; r < NT; r++) {
            int n = blockIdx.x * (32*NT) + r*32 + ns;
            nrow[r] = n;
            const ulonglong2* row = (const ulonglong2*)(g_pred_cp + ((size_t)b*N_ + n) * CPD);
            ulonglong2 u0 = row[0], u1 = row[1], u2 = row[2], u3 = row[3];
            FP[r][0] = u0.x; FP[r][1] = u0.y;
            FP[r][2] = u1.x; FP[r][3] = u1.y;
            FP[r][4] = u2.x; FP[r][5] = u2.y;
            FP[r][6] = u3.x;
            float fa, fb_; unpack2(u3.y, fa, fb_);
            f14[r] = fa; fn[r] = fb_;
            float f6, f7, f8, f9, f10, f11;
            unpack2(u1.y, f6, f7); unpack2(u2.x, f8, f9); unpack2(u2.y, f10, f11);
            fD0[r] = f6 - f9; fD1[r] = f7 - f10; fD2[r] = f8 - f11;
        }
        float minv[NT];
        #pragma unroll
        for (int r = 0; r < NT; r++) minv[r] = F_INF;

        int nch = g_nch[b];
        for (int c = half; c < nch; c += 2) {
            int mc = c * CH;
            __syncthreads();
            const float4* src = (const float4*)(g_gt_c + ((size_t)b*N_ + mc) * CPD);
            #pragma unroll
            for (int j = tid; j < CH*4; j += 256) sg[(j >> 2) * 5 + (j & 3)] = src[j];
            __syncthreads();
            for (int j = tid; j < CH; j += 256) {
                float4 s1 = sg[j*5+1], s2 = sg[j*5+2];
                sg[j*5+4] = make_float4(s1.z - s2.y, s1.w - s2.z, s2.x - s2.w, 0.f);
            }
            __syncthreads();

            #pragma unroll 2
            for (int j = 0; j < CH/8; j++) {
                int m = ml + j*8;
                const char* pb = (const char*)&sg[m*5];
                ulonglong2 U0 = *(const ulonglong2*)(pb);
                ulonglong2 U1 = *(const ulonglong2*)(pb + 16);
                ulonglong2 U2 = *(const ulonglong2*)(pb + 32);
                ulonglong2 U3 = *(const ulonglong2*)(pb + 48);
                float4 dx = *(const float4*)(pb + 64);
                float s14, sn; unpack2(U3.y, s14, sn);

                #pragma unroll
                for (int r = 0; r < NT; r++) {
                    ull a = mul2(FP[r][0], U0.x);
                    ull cc = mul2(FP[r][1], U0.y);
                    a = fma2(FP[r][2], U1.x, a);
                    cc = fma2(FP[r][3], U1.y, cc);
                    a = fma2(FP[r][4], U2.x, a);
                    cc = fma2(FP[r][5], U2.y, cc);
                    a = fma2(FP[r][6], U3.x, a);
                    float alo, ahi, clo, chi;
                    unpack2(a, alo, ahi); unpack2(cc, clo, chi);
                    float dot = fmaf(f14[r], s14, (alo + ahi) + (clo + chi));
                    float d1 = fmaf(-2.0f, dot, fn[r] + sn);
                    float corr = fD0[r] * dx.x;
                    corr = fmaf(fD1[r], dx.y, corr);
                    corr = fmaf(fD2[r], dx.z, corr);
                    float d2 = fmaf(2.0f, corr, d1);
                    minv[r] = fminf(minv[r], fminf(d1, d2));   // clamp deferred
                }
            }
        }
        #pragma unroll
        for (int r = 0; r < NT; r++) {
            float v = minv[r];
            v = fminf(v, __shfl_down_sync(0xffffffffu, v, 4));
            v = fminf(v, __shfl_down_sync(0xffffffffu, v, 2));
            v = fminf(v, __shfl_down_sync(0xffffffffu, v, 1));
            if (ml == 0)
                atomicMin(&g_best_u[(size_t)b*N_ + nrow[r]], __float_as_uint(fmaxf(v, 0.0f)));
        }
    } else {
        // ---------------- direction B ----------------
        int quart = z - 2;
        int padcnt = g_nch[b] * CH;
        int row0 = blockIdx.x * (32*NT);
        if (row0 >= padcnt) return;

        ull FP[NT][7];
        float f14[NT], fn[NT], fD0[NT], fD1[NT], fD2[NT];
        int orig[NT];
        #pragma unroll
        for (int r = 0; r < NT; r++) {
            int n = row0 + r*32 + ns;
            orig[r] = g_cidx[(size_t)b*N_ + n];
            const ulonglong2* row = (const ulonglong2*)(g_gt_c + ((size_t)b*N_ + n) * CPD);
            ulonglong2 u0 = row[0], u1 = row[1], u2 = row[2], u3 = row[3];
            FP[r][0] = u0.x; FP[r][1] = u0.y;
            FP[r][2] = u1.x; FP[r][3] = u1.y;
            FP[r][4] = u2.x; FP[r][5] = u2.y;
            FP[r][6] = u3.x;
            float fa, fb_; unpack2(u3.y, fa, fb_);
            f14[r] = fa; fn[r] = fb_;
            float f6, f7, f8, f9, f10, f11;
            unpack2(u1.y, f6, f7); unpack2(u2.x, f8, f9); unpack2(u2.y, f10, f11);
            fD0[r] = f6 - f9; fD1[r] = f7 - f10; fD2[r] = f8 - f11;
        }
        ull b1[NT], b2[NT];
        #pragma unroll
        for (int r = 0; r < NT; r++) { b1[r] = ~0ull; b2[r] = ~0ull; }

        for (int c = quart; c < N_/CH; c += 4) {
            int mc = c * CH;
            __syncthreads();
            const float4* src = (const float4*)(g_pred_cp + ((size_t)b*N_ + mc) * CPD);
            #pragma unroll
            for (int j = tid; j < CH*4; j += 256) sg[(j >> 2) * 5 + (j & 3)] = src[j];
            __syncthreads();
            for (int j = tid; j < CH; j += 256) {
                float4 s1 = sg[j*5+1], s2 = sg[j*5+2];
                sg[j*5+4] = make_float4(s1.z - s2.y, s1.w - s2.z, s2.x - s2.w, 0.f);
            }
            __syncthreads();

            #pragma unroll 2
            for (int j = 0; j < CH/8; j++) {
                int m = ml + j*8;
                const char* pb = (const char*)&sg[m*5];
                ulonglong2 U0 = *(const ulonglong2*)(pb);
                ulonglong2 U1 = *(const ulonglong2*)(pb + 16);
                ulonglong2 U2 = *(const ulonglong2*)(pb + 32);
                ulonglong2 U3 = *(const ulonglong2*)(pb + 48);
                float4 dx = *(const float4*)(pb + 64);
                float s14, sn; unpack2(U3.y, s14, sn);
                unsigned idx = (unsigned)(mc + m);

                #pragma unroll
                for (int r = 0; r < NT; r++) {
                    ull a = mul2(FP[r][0], U0.x);
                    ull cc = mul2(FP[r][1], U0.y);
                    a = fma2(FP[r][2], U1.x, a);
                    cc = fma2(FP[r][3], U1.y, cc);
                    a = fma2(FP[r][4], U2.x, a);
                    cc = fma2(FP[r][5], U2.y, cc);
                    a = fma2(FP[r][6], U3.x, a);
                    float alo, ahi, clo, chi;
                    unpack2(a, alo, ahi); unpack2(cc, clo, chi);
                    float dot = fmaf(f14[r], s14, (alo + ahi) + (clo + chi));
                    float d1 = fmaf(-2.0f, dot, fn[r] + sn);
                    float corr = fD0[r] * dx.x;
                    corr = fmaf(fD1[r], dx.y, corr);
                    corr = fmaf(fD2[r], dx.z, corr);
                    float d2 = fmaf(2.0f, corr, d1);
                    d1 = fmaxf(d1, 0.0f);
                    d2 = fmaxf(d2, 0.0f);
                    ull k1 = ((ull)__float_as_uint(d1) << 32) | idx;
                    ull k2 = ((ull)__float_as_uint(d2) << 32) | idx;
                    if (k1 < b1[r]) b1[r] = k1;
                    if (k2 < b2[r]) b2[r] = k2;
                }
            }
        }
        #pragma unroll
        for (int r = 0; r < NT; r++) {
            ull v1 = b1[r], v2 = b2[r], o;
            o = __shfl_down_sync(0xffffffffu, v1, 4); if (o < v1) v1 = o;
            o = __shfl_down_sync(0xffffffffu, v1, 2); if (o < v1) v1 = o;
            o = __shfl_down_sync(0xffffffffu, v1, 1); if (o < v1) v1 = o;
            o = __shfl_down_sync(0xffffffffu, v2, 4); if (o < v2) v2 = o;
            o = __shfl_down_sync(0xffffffffu, v2, 2); if (o < v2) v2 = o;
            o = __shfl_down_sync(0xffffffffu, v2, 1); if (o < v2) v2 = o;
            if (ml == 0) {
                atomicMin(&g_k1[(size_t)b*N_ + orig[r]], v1);
                atomicMin(&g_k2[(size_t)b*N_ + orig[r]], v2);
            }
        }
    }
}

// ---------------- kernel 3: fused final reduction (last-block combine) ----------------
__global__ void final_kernel(const float* __restrict__ succ,
                             const float* __restrict__ bsp,
                             float* __restrict__ out)
{
#if __CUDA_ARCH__ >= 900
    cudaGridDependencySynchronize();
#endif
    int i = blockIdx.x * 256 + threadIdx.x;   // block -> contiguous 256, same batch
    int b = i >> 11;
    float sv = succ[i];
    float ev = g_ew[i];
    ull k1 = g_k1[i], k2 = g_k2[i];           // unconditional: overlap latency
    unsigned bu = g_best_u[i];
    float cv = g_sbce[i];

    float gv = 0.0f;
    if (sv > 0.5f) {
        float m1 = __uint_as_float((unsigned)(k1 >> 32));
        float m2 = __uint_as_float((unsigned)(k2 >> 32));
        int i1 = (int)(k1 & 0xFFFFFFFFu);
        int i2 = (int)(k2 & 0xFFFFFFFFu);
        int idx = (m2 < m1) ? i2 : i1;
        gv = sv * bsp[(size_t)b*N_ + idx] * fminf(m1, m2);
    }

    float ma = (bu == 0x7f800000u) ? 0.0f : sqrtf(__uint_as_float(bu));
    float av = bsp[i] * ma;

    #define WR(v) { v += __shfl_xor_sync(0xffffffffu, v, 16); \
                    v += __shfl_xor_sync(0xffffffffu, v, 8);  \
                    v += __shfl_xor_sync(0xffffffffu, v, 4);  \
                    v += __shfl_xor_sync(0xffffffffu, v, 2);  \
                    v += __shfl_xor_sync(0xffffffffu, v, 1); }
    WR(sv) WR(ev) WR(gv) WR(av) WR(cv)
    #undef WR

    __shared__ float red[8][5];
    __shared__ bool amLast;
    int w = threadIdx.x >> 5, l = threadIdx.x & 31;
    if (l == 0) { red[w][0]=sv; red[w][1]=ev; red[w][2]=gv; red[w][3]=av; red[w][4]=cv; }
    __syncthreads();

    if (threadIdx.x == 0) {
        float a0=0,a1=0,a2=0,a3=0,a4=0;
        #pragma unroll
        for (int w2 = 0; w2 < 8; w2++) {
            a0+=red[w2][0]; a1+=red[w2][1]; a2+=red[w2][2]; a3+=red[w2][3]; a4+=red[w2][4];
        }
        g_part[blockIdx.x][0]=a0; g_part[blockIdx.x][1]=a1; g_part[blockIdx.x][2]=a2;
        g_part[blockIdx.x][3]=a3; g_part[blockIdx.x][4]=a4;
        __threadfence();
        amLast = (atomicAdd(&g_done, 1u) == NRED - 1);
    }
    __syncthreads();

    if (amLast && threadIdx.x < 32) {
        int t = threadIdx.x;
        __threadfence();
        float s  = __ldcg(&g_part[t][0]);
        float e  = __ldcg(&g_part[t][1]);
        float g  = __ldcg(&g_part[t][2]);
        float ad = __ldcg(&g_part[t][3]);
        float bc = __ldcg(&g_part[t][4]);

        // per-batch sums: groups of 8 consecutive lanes
        s += __shfl_xor_sync(0xffffffffu, s, 1); s += __shfl_xor_sync(0xffffffffu, s, 2); s += __shfl_xor_sync(0xffffffffu, s, 4);
        e += __shfl_xor_sync(0xffffffffu, e, 1); e += __shfl_xor_sync(0xffffffffu, e, 2); e += __shfl_xor_sync(0xffffffffu, e, 4);
        g += __shfl_xor_sync(0xffffffffu, g, 1); g += __shfl_xor_sync(0xffffffffu, g, 2); g += __shfl_xor_sync(0xffffffffu, g, 4);
        // global sums
        ad += __shfl_xor_sync(0xffffffffu, ad, 1); ad += __shfl_xor_sync(0xffffffffu, ad, 2);
        ad += __shfl_xor_sync(0xffffffffu, ad, 4); ad += __shfl_xor_sync(0xffffffffu, ad, 8);
        ad += __shfl_xor_sync(0xffffffffu, ad, 16);
        bc += __shfl_xor_sync(0xffffffffu, bc, 1); bc += __shfl_xor_sync(0xffffffffu, bc, 2);
        bc += __shfl_xor_sync(0xffffffffu, bc, 4); bc += __shfl_xor_sync(0xffffffffu, bc, 8);
        bc += __shfl_xor_sync(0xffffffffu, bc, 16);

        float S0 = __shfl_sync(0xffffffffu, s, 0),  E0 = __shfl_sync(0xffffffffu, e, 0),  G0 = __shfl_sync(0xffffffffu, g, 0);
        float S1 = __shfl_sync(0xffffffffu, s, 8),  E1 = __shfl_sync(0xffffffffu, e, 8),  G1 = __shfl_sync(0xffffffffu, g, 8);
        float S2 = __shfl_sync(0xffffffffu, s, 16), E2 = __shfl_sync(0xffffffffu, e, 16), G2 = __shfl_sync(0xffffffffu, g, 16);
        float S3 = __shfl_sync(0xffffffffu, s, 24), E3 = __shfl_sync(0xffffffffu, e, 24), G3 = __shfl_sync(0xffffffffu, g, 24);

        if (t == 0) {
            float tot = (E0 + G0) / fmaxf(S0, 1.0f)
                      + (E1 + G1) / fmaxf(S1, 1.0f)
                      + (E2 + G2) / fmaxf(S2, 1.0f)
                      + (E3 + G3) / fmaxf(S3, 1.0f);
            tot *= (1.0f / B_);
            tot += 10.0f * ad * (1.0f / (B_ * N_));
            tot += bc * (1.0f / (B_ * N_));
            out[0] = tot;
        }
    }
}

// ---------------- launch (PDL chain: prep -> pair -> final) ----------------
extern "C" void kernel_launch(void* const* d_in, const int* in_sizes, int n_in,
                              void* d_out, int out_size)
{
    const float* gd   = (const float*)d_in[0];
    const float* ad   = (const float*)d_in[1];
    const float* goh  = (const float*)d_in[2];
    const float* pp   = (const float*)d_in[3];
    const float* bsp  = (const float*)d_in[4];
    const float* bsh  = (const float*)d_in[5];
    const float* dl   = (const float*)d_in[6];
    const float* ol   = (const float*)d_in[7];
    const float* succ = (const float*)d_in[8];
    const float* al   = (const float*)d_in[9];
    const float* bv   = (const float*)d_in[10];
    const float* bw   = (const float*)d_in[11];
    const float* cp   = (const float*)d_in[12];
    float* out = (float*)d_out;

    prep_kernel<<<128, 128>>>(gd, ad, goh, pp, bsh, dl, ol, succ, al, bv, bw, cp);

    cudaLaunchAttribute attr[1];
    attr[0].id = cudaLaunchAttributeProgrammaticStreamSerialization;
    attr[0].val.programmaticStreamSerializationAllowed = 1;

    cudaLaunchConfig_t cfg2 = {};
    cfg2.gridDim  = dim3(N_ / (32*NT), B_, 6);
    cfg2.blockDim = dim3(256, 1, 1);
    cfg2.attrs = attr;
    cfg2.numAttrs = 1;
    cudaLaunchKernelEx(&cfg2, pair_kernel, bsp);

    cudaLaunchConfig_t cfg3 = {};
    cfg3.gridDim  = dim3(NRED, 1, 1);
    cfg3.blockDim = dim3(256, 1, 1);
    cfg3.attrs = attr;
    cfg3.numAttrs = 1;
    cudaLaunchKernelEx(&cfg3, final_kernel, succ, bsp, out);
}